// round 10
// baseline (speedup 1.0000x reference)
#include <cuda_runtime.h>
#include <cuda_bf16.h>
#include <math.h>
#include <cstdint>

#define kS  1024
#define kB  4
#define kD  1024
#define kH  16
#define kDH 64

// bf16 split scratch (hi + residual-lo)
__device__ __nv_bfloat16 g_qa_hi[kS*kB*kD], g_qa_lo[kS*kB*kD];   // activations
__device__ __nv_bfloat16 g_ka_hi[kS*kB*kD], g_ka_lo[kS*kB*kD];
__device__ __nv_bfloat16 g_va_hi[kS*kB*kD], g_va_lo[kS*kB*kD];
__device__ __nv_bfloat16 g_oa_hi[kS*kB*kD], g_oa_lo[kS*kB*kD];   // attn out (concat)
__device__ __nv_bfloat16 g_wq_hi[kH*kDH*kD], g_wq_lo[kH*kDH*kD]; // [h][n][k]
__device__ __nv_bfloat16 g_wk_hi[kH*kDH*kD], g_wk_lo[kH*kDH*kD];
__device__ __nv_bfloat16 g_wv_hi[kH*kDH*kD], g_wv_lo[kH*kDH*kD];
__device__ __nv_bfloat16 g_wo_hi[kD*kD],     g_wo_lo[kD*kD];     // [n][k]
// projected q/k/v in bf16 split
__device__ __nv_bfloat16 g_qp_hi[kB*kH*kS*kDH], g_qp_lo[kB*kH*kS*kDH]; // [b][h][s][dh]
__device__ __nv_bfloat16 g_kp_hi[kB*kH*kS*kDH], g_kp_lo[kB*kH*kS*kDH]; // [b][h][s][dh]
__device__ __nv_bfloat16 g_vp_hi[kB*kH*kS*kDH], g_vp_lo[kB*kH*kS*kDH]; // [b][h][dh][s]

// ===================== helpers =====================
__device__ __forceinline__ uint32_t smem_u32(const void* p) {
    uint32_t a;
    asm("{ .reg .u64 t; cvta.to.shared.u64 t, %1; cvt.u32.u64 %0, t; }" : "=r"(a) : "l"(p));
    return a;
}
__device__ __forceinline__ void ldmatrix_x4(uint32_t* r, uint32_t a) {
    asm volatile("ldmatrix.sync.aligned.m8n8.x4.shared.b16 {%0,%1,%2,%3}, [%4];"
        : "=r"(r[0]), "=r"(r[1]), "=r"(r[2]), "=r"(r[3]) : "r"(a));
}
__device__ __forceinline__ void mma_bf16(float* c, const uint32_t* a, const uint32_t* b) {
    asm volatile("mma.sync.aligned.m16n8k16.row.col.f32.bf16.bf16.f32 "
        "{%0,%1,%2,%3},{%4,%5,%6,%7},{%8,%9},{%0,%1,%2,%3};"
        : "+f"(c[0]), "+f"(c[1]), "+f"(c[2]), "+f"(c[3])
        : "r"(a[0]), "r"(a[1]), "r"(a[2]), "r"(a[3]), "r"(b[0]), "r"(b[1]));
}
__device__ __forceinline__ void split_pack(float x, float y, uint32_t& hp, uint32_t& lp) {
    __nv_bfloat16 hx = __float2bfloat16_rn(x);
    __nv_bfloat16 hy = __float2bfloat16_rn(y);
    __nv_bfloat16 lx = __float2bfloat16_rn(x - __bfloat162float(hx));
    __nv_bfloat16 ly = __float2bfloat16_rn(y - __bfloat162float(hy));
    hp = (uint32_t)__bfloat16_as_ushort(hx) | ((uint32_t)__bfloat16_as_ushort(hy) << 16);
    lp = (uint32_t)__bfloat16_as_ushort(lx) | ((uint32_t)__bfloat16_as_ushort(ly) << 16);
}
__device__ __forceinline__ void cp_async16(uint32_t saddr, const void* gptr) {
    asm volatile("cp.async.cg.shared.global [%0], [%1], 16;" :: "r"(saddr), "l"(gptr));
}
#define CP_COMMIT() asm volatile("cp.async.commit_group;" ::: "memory")
#define CP_WAIT_1() asm volatile("cp.async.wait_group 1;" ::: "memory")
#define CP_WAIT_0() asm volatile("cp.async.wait_group 0;" ::: "memory")

// swizzled offset within 128B-wide rows: seg XOR (row&7)
__device__ __forceinline__ uint32_t sw_off(int row, int seg) {
    return (uint32_t)(row * 128 + ((seg ^ (row & 7)) << 4));
}

// ===========================================================================
// Prep 1: split q/k/v activations. grid (n4/256, 3)
// ===========================================================================
__global__ void __launch_bounds__(256) split3_kernel(
    const float* __restrict__ q, const float* __restrict__ k,
    const float* __restrict__ v, int n4)
{
    int which = blockIdx.y;
    const float* src = (which == 0) ? q : (which == 1) ? k : v;
    __nv_bfloat16* hi = (which == 0) ? g_qa_hi : (which == 1) ? g_ka_hi : g_va_hi;
    __nv_bfloat16* lo = (which == 0) ? g_qa_lo : (which == 1) ? g_ka_lo : g_va_lo;
    int i = blockIdx.x * blockDim.x + threadIdx.x;
    if (i >= n4) return;
    float4 vv = ((const float4*)src)[i];
    uint32_t h0, l0, h1, l1;
    split_pack(vv.x, vv.y, h0, l0);
    split_pack(vv.z, vv.w, h1, l1);
    *(uint2*)(hi + (size_t)i * 4) = make_uint2(h0, h1);
    *(uint2*)(lo + (size_t)i * 4) = make_uint2(l0, l1);
}

// ===========================================================================
// Prep 2: transpose+split weights
// ===========================================================================
__global__ void __launch_bounds__(256) transpose_wqkv_kernel(
    const float* __restrict__ Wq, const float* __restrict__ Wk,
    const float* __restrict__ Wv)
{
    __shared__ float tile[32][33];
    int which = blockIdx.z >> 4;
    int h = blockIdx.z & 15;
    const float* src = ((which == 0) ? Wq : (which == 1) ? Wk : Wv) + (size_t)h * kD * kDH;
    __nv_bfloat16* hi = ((which == 0) ? g_wq_hi : (which == 1) ? g_wk_hi : g_wv_hi) + (size_t)h * kDH * kD;
    __nv_bfloat16* lo = ((which == 0) ? g_wq_lo : (which == 1) ? g_wk_lo : g_wv_lo) + (size_t)h * kDH * kD;
    int c0 = blockIdx.x * 32, r0 = blockIdx.y * 32;
    int tx = threadIdx.x, ty = threadIdx.y;
    #pragma unroll
    for (int i = 0; i < 4; i++)
        tile[ty + i * 8][tx] = src[(size_t)(r0 + ty + i * 8) * kDH + c0 + tx];
    __syncthreads();
    #pragma unroll
    for (int i = 0; i < 4; i++) {
        float v = tile[tx][ty + i * 8];
        __nv_bfloat16 hv = __float2bfloat16_rn(v);
        __nv_bfloat16 lv = __float2bfloat16_rn(v - __bfloat162float(hv));
        size_t o = (size_t)(c0 + ty + i * 8) * kD + r0 + tx;
        hi[o] = hv;
        lo[o] = lv;
    }
}

__global__ void __launch_bounds__(256) transpose_wo_kernel(const float* __restrict__ Wo)
{
    __shared__ float tile[32][33];
    int c0 = blockIdx.x * 32, r0 = blockIdx.y * 32;
    int tx = threadIdx.x, ty = threadIdx.y;
    #pragma unroll
    for (int i = 0; i < 4; i++)
        tile[ty + i * 8][tx] = Wo[(size_t)(r0 + ty + i * 8) * kD + c0 + tx];
    __syncthreads();
    #pragma unroll
    for (int i = 0; i < 4; i++) {
        float v = tile[tx][ty + i * 8];
        __nv_bfloat16 hv = __float2bfloat16_rn(v);
        __nv_bfloat16 lv = __float2bfloat16_rn(v - __bfloat162float(hv));
        size_t o = (size_t)(c0 + ty + i * 8) * kD + r0 + tx;
        g_wo_hi[o] = hv;
        g_wo_lo[o] = lv;
    }
}

// ===========================================================================
// mma.sync GEMM, 3-stage cp.async pipeline, BK=32, 1 sync/chunk.
// Row layout: 128B rows = [32k hi (segs 0-3) | 32k lo (segs 4-7)], XOR swizzle.
// Stage: A 128 rows @0 (16KB), B 64 rows @16384 (8KB). 3 stages = 72KB -> 3 CTAs.
// ===========================================================================
#define G_A 0
#define G_B 16384
#define G_STG 24576
#define GEMM_SMEM (3 * G_STG)   // 73728

__device__ __forceinline__ void gemm_compute_chunk(
    uint32_t stb, int wm, int wn, int lane, float acc[2][4][4])
{
    int lrow = lane & 15;
    int lseg = lane >> 4;
    #pragma unroll
    for (int ks = 0; ks < 2; ks++) {
        int seg = ks * 2 + lseg;          // hi: 0..3 ; lo: +4
        uint32_t a0f[2][4], a1f[2][4], b0f[4][2], b1f[4][2];
        #pragma unroll
        for (int mt = 0; mt < 2; mt++) {
            int row = wm * 32 + mt * 16 + lrow;
            ldmatrix_x4(a0f[mt], stb + G_A + sw_off(row, seg));
            ldmatrix_x4(a1f[mt], stb + G_A + sw_off(row, seg + 4));
        }
        #pragma unroll
        for (int nt2 = 0; nt2 < 2; nt2++) {
            int row = wn * 32 + nt2 * 16 + lrow;
            uint32_t t[4];
            ldmatrix_x4(t, stb + G_B + sw_off(row, seg));
            b0f[nt2 * 2 + 0][0] = t[0]; b0f[nt2 * 2 + 0][1] = t[2];
            b0f[nt2 * 2 + 1][0] = t[1]; b0f[nt2 * 2 + 1][1] = t[3];
            ldmatrix_x4(t, stb + G_B + sw_off(row, seg + 4));
            b1f[nt2 * 2 + 0][0] = t[0]; b1f[nt2 * 2 + 0][1] = t[2];
            b1f[nt2 * 2 + 1][0] = t[1]; b1f[nt2 * 2 + 1][1] = t[3];
        }
        #pragma unroll
        for (int mt = 0; mt < 2; mt++)
            #pragma unroll
            for (int nt = 0; nt < 4; nt++) {
                mma_bf16(acc[mt][nt], a0f[mt], b0f[nt]);
                mma_bf16(acc[mt][nt], a0f[mt], b1f[nt]);
                mma_bf16(acc[mt][nt], a1f[mt], b0f[nt]);
            }
    }
}

// ---- fused projections. grid (8, 48, 4): y -> which*16+h ----
__global__ void __launch_bounds__(256, 3) proj_mma_kernel(
    const float* __restrict__ bq, const float* __restrict__ bk,
    const float* __restrict__ bv)
{
    extern __shared__ char smem[];
    uint32_t sbase = smem_u32(smem);
    int s0 = blockIdx.x * 128;
    int which = blockIdx.y >> 4;
    int h  = blockIdx.y & 15;
    int b  = blockIdx.z;
    int tid = threadIdx.x;
    int wid = tid >> 5, lane = tid & 31;
    int wm = wid >> 1, wn = wid & 1;

    const __nv_bfloat16* a_hi = (which == 0) ? g_qa_hi : (which == 1) ? g_ka_hi : g_va_hi;
    const __nv_bfloat16* a_lo = (which == 0) ? g_qa_lo : (which == 1) ? g_ka_lo : g_va_lo;
    const __nv_bfloat16* w_hi = (which == 0) ? g_wq_hi : (which == 1) ? g_wk_hi : g_wv_hi;
    const __nv_bfloat16* w_lo = (which == 0) ? g_wq_lo : (which == 1) ? g_wk_lo : g_wv_lo;
    const float* bias = (which == 0) ? bq : (which == 1) ? bk : bv;

    float acc[2][4][4];
    #pragma unroll
    for (int mt = 0; mt < 2; mt++)
        #pragma unroll
        for (int nt = 0; nt < 4; nt++)
            #pragma unroll
            for (int e = 0; e < 4; e++) acc[mt][nt][e] = 0.f;

    auto load_chunk = [&](int c, int stg) {
        uint32_t stb = sbase + stg * G_STG;
        int k0 = c * 32;
        #pragma unroll
        for (int i = 0; i < 2; i++) {
            int id = tid + i * 256;
            int m = id >> 2, k8 = id & 3;
            size_t g = ((size_t)(s0 + m) * kB + b) * kD + k0 + k8 * 8;
            cp_async16(stb + G_A + sw_off(m, k8), a_hi + g);
            cp_async16(stb + G_A + sw_off(m, k8 + 4), a_lo + g);
        }
        {
            int n = tid >> 2, k8 = tid & 3;
            size_t g = ((size_t)h * kDH + n) * kD + k0 + k8 * 8;
            cp_async16(stb + G_B + sw_off(n, k8), w_hi + g);
            cp_async16(stb + G_B + sw_off(n, k8 + 4), w_lo + g);
        }
    };

    load_chunk(0, 0); CP_COMMIT();
    load_chunk(1, 1); CP_COMMIT();
    for (int c = 0; c < 32; c++) {
        CP_WAIT_1();
        __syncthreads();
        if (c + 2 < 32) load_chunk(c + 2, (c + 2) % 3);
        CP_COMMIT();
        gemm_compute_chunk(sbase + (c % 3) * G_STG, wm, wn, lane, acc);
    }

    int gq = lane >> 2, tg = lane & 3;
    size_t bh = (size_t)b * kH + h;
    if (which < 2) {
        __nv_bfloat16* oh = (which == 0) ? g_qp_hi : g_kp_hi;
        __nv_bfloat16* ol = (which == 0) ? g_qp_lo : g_kp_lo;
        #pragma unroll
        for (int mt = 0; mt < 2; mt++) {
            int row0 = s0 + wm * 32 + mt * 16 + gq;
            #pragma unroll
            for (int nt = 0; nt < 4; nt++) {
                int col = wn * 32 + nt * 8 + tg * 2;
                float b0 = bias[h * kDH + col], b1 = bias[h * kDH + col + 1];
                uint32_t hp, lp;
                size_t off0 = (bh * kS + row0) * kDH + col;
                split_pack(acc[mt][nt][0] + b0, acc[mt][nt][1] + b1, hp, lp);
                *(uint32_t*)(oh + off0) = hp; *(uint32_t*)(ol + off0) = lp;
                split_pack(acc[mt][nt][2] + b0, acc[mt][nt][3] + b1, hp, lp);
                size_t off1 = off0 + (size_t)8 * kDH;
                *(uint32_t*)(oh + off1) = hp; *(uint32_t*)(ol + off1) = lp;
            }
        }
    } else {
        #pragma unroll
        for (int mt = 0; mt < 2; mt++) {
            int row0 = s0 + wm * 32 + mt * 16 + gq;
            #pragma unroll
            for (int nt = 0; nt < 4; nt++) {
                int col = wn * 32 + nt * 8 + tg * 2;
                float b0 = bias[h * kDH + col], b1 = bias[h * kDH + col + 1];
                float vals[4] = {acc[mt][nt][0] + b0, acc[mt][nt][1] + b1,
                                 acc[mt][nt][2] + b0, acc[mt][nt][3] + b1};
                int rr[4] = {row0, row0, row0 + 8, row0 + 8};
                int cc[4] = {col, col + 1, col, col + 1};
                #pragma unroll
                for (int e = 0; e < 4; e++) {
                    __nv_bfloat16 hv = __float2bfloat16_rn(vals[e]);
                    __nv_bfloat16 lv = __float2bfloat16_rn(vals[e] - __bfloat162float(hv));
                    size_t off = (bh * kDH + cc[e]) * kS + rr[e];
                    g_vp_hi[off] = hv;
                    g_vp_lo[off] = lv;
                }
            }
        }
    }
}

// ---- output projection ----
__global__ void __launch_bounds__(256, 3) outproj_mma_kernel(
    const float* __restrict__ bo, float* __restrict__ out)
{
    extern __shared__ char smem[];
    uint32_t sbase = smem_u32(smem);
    int m0 = blockIdx.x * 128;
    int n0 = blockIdx.y * 64;
    int tid = threadIdx.x;
    int wid = tid >> 5, lane = tid & 31;
    int wm = wid >> 1, wn = wid & 1;

    float acc[2][4][4];
    #pragma unroll
    for (int mt = 0; mt < 2; mt++)
        #pragma unroll
        for (int nt = 0; nt < 4; nt++)
            #pragma unroll
            for (int e = 0; e < 4; e++) acc[mt][nt][e] = 0.f;

    auto load_chunk = [&](int c, int stg) {
        uint32_t stb = sbase + stg * G_STG;
        int k0 = c * 32;
        #pragma unroll
        for (int i = 0; i < 2; i++) {
            int id = tid + i * 256;
            int m = id >> 2, k8 = id & 3;
            size_t g = (size_t)(m0 + m) * kD + k0 + k8 * 8;
            cp_async16(stb + G_A + sw_off(m, k8), g_oa_hi + g);
            cp_async16(stb + G_A + sw_off(m, k8 + 4), g_oa_lo + g);
        }
        {
            int n = tid >> 2, k8 = tid & 3;
            size_t g = (size_t)(n0 + n) * kD + k0 + k8 * 8;
            cp_async16(stb + G_B + sw_off(n, k8), g_wo_hi + g);
            cp_async16(stb + G_B + sw_off(n, k8 + 4), g_wo_lo + g);
        }
    };

    load_chunk(0, 0); CP_COMMIT();
    load_chunk(1, 1); CP_COMMIT();
    for (int c = 0; c < 32; c++) {
        CP_WAIT_1();
        __syncthreads();
        if (c + 2 < 32) load_chunk(c + 2, (c + 2) % 3);
        CP_COMMIT();
        gemm_compute_chunk(sbase + (c % 3) * G_STG, wm, wn, lane, acc);
    }

    int gq = lane >> 2, tg = lane & 3;
    #pragma unroll
    for (int mt = 0; mt < 2; mt++) {
        int row = m0 + wm * 32 + mt * 16 + gq;
        #pragma unroll
        for (int nt = 0; nt < 4; nt++) {
            int col = n0 + wn * 32 + nt * 8 + tg * 2;
            float b0 = bo[col], b1 = bo[col + 1];
            size_t r0 = (size_t)row * kD + col;
            *(float2*)(out + r0) = make_float2(acc[mt][nt][0] + b0, acc[mt][nt][1] + b1);
            *(float2*)(out + r0 + 8 * kD) = make_float2(acc[mt][nt][2] + b0, acc[mt][nt][3] + b1);
        }
    }
}

// ===========================================================================
// Tensor-core attention, 3-stage cp.async K/V pipeline, 1 sync/tile.
// Stage (32KB): K_hi 0, K_lo 8192, V_hi 16384, V_lo 24576. 3 stages = 96KB.
// Mask at 98304 (4KB). Total 100KB -> 2 CTAs/SM.
// ===========================================================================
#define AK_HI 0
#define AK_LO 8192
#define AV_HI 16384
#define AV_LO 24576
#define ASTG  32768
#define AMK   98304
#define ATTN_SMEM (98304 + 4096)

__global__ void __launch_bounds__(256) attn_mma_kernel(const int* __restrict__ mask)
{
    extern __shared__ char smem[];
    uint32_t sbase = smem_u32(smem);
    int s0 = blockIdx.x * 128;
    int h  = blockIdx.y;
    int b  = blockIdx.z;
    int tid = threadIdx.x;
    int w = tid >> 5, lane = tid & 31;
    int gq = lane >> 2, tg = lane & 3;
    size_t bh = (size_t)b * kH + h;

    const __nv_bfloat16* qh = g_qp_hi + bh * kS * kDH;
    const __nv_bfloat16* ql = g_qp_lo + bh * kS * kDH;
    const __nv_bfloat16* kh = g_kp_hi + bh * kS * kDH;
    const __nv_bfloat16* kl = g_kp_lo + bh * kS * kDH;
    const __nv_bfloat16* vth = g_vp_hi + bh * kDH * kS;  // [dh][s]
    const __nv_bfloat16* vtl = g_vp_lo + bh * kDH * kS;

    // ---- mask preload ----
    float* Mk = (float*)(smem + AMK);
    for (int idx = tid; idx < kS; idx += 256)
        Mk[idx] = (float)mask[(size_t)idx * kB + b] * 1e18f;

    // ---- stage Q tile (128 rows hi at 0, lo at 16384; swizzled) ----
    #pragma unroll
    for (int i = 0; i < 4; i++) {
        int id = tid + i * 256;
        int row = id >> 3, k8 = id & 7;
        size_t g = (size_t)(s0 + row) * kDH + k8 * 8;
        uint32_t d = sbase + sw_off(row, k8);
        cp_async16(d, qh + g);
        cp_async16(d + 16384, ql + g);
    }
    CP_COMMIT();
    CP_WAIT_0();
    __syncthreads();
    uint32_t qfh[4][4], qfl[4][4];
    int lrow = lane & 15, lseg = lane >> 4;
    #pragma unroll
    for (int ks = 0; ks < 4; ks++) {
        uint32_t addr = sbase + sw_off(w * 16 + lrow, ks * 2 + lseg);
        ldmatrix_x4(qfh[ks], addr);
        ldmatrix_x4(qfl[ks], addr + 16384);
    }
    __syncthreads();  // Q reads done before stage reuse

    float acc_o[8][4];
    #pragma unroll
    for (int nt = 0; nt < 8; nt++)
        #pragma unroll
        for (int e = 0; e < 4; e++) acc_o[nt][e] = 0.f;
    float l_run[2] = {0.f, 0.f};
    const float scale = 0.125f;

    auto load_tile = [&](int t, int stg) {
        uint32_t stb = sbase + stg * ASTG;
        int j0 = t * 64;
        #pragma unroll
        for (int i = 0; i < 8; i++) {
            int id = tid + (i & 1) * 256;
            int row = id >> 3, k8 = id & 7;
            const __nv_bfloat16* src;
            uint32_t dst;
            if (i < 2)      { src = kh  + (size_t)(j0 + row) * kDH + k8 * 8; dst = AK_HI; }
            else if (i < 4) { src = kl  + (size_t)(j0 + row) * kDH + k8 * 8; dst = AK_LO; }
            else if (i < 6) { src = vth + (size_t)row * kS + j0 + k8 * 8;    dst = AV_HI; }
            else            { src = vtl + (size_t)row * kS + j0 + k8 * 8;    dst = AV_LO; }
            cp_async16(stb + dst + sw_off(row, k8), src);
        }
    };

    load_tile(0, 0); CP_COMMIT();
    load_tile(1, 1); CP_COMMIT();
    for (int t = 0; t < 16; t++) {
        CP_WAIT_1();
        __syncthreads();
        if (t + 2 < 16) load_tile(t + 2, (t + 2) % 3);
        CP_COMMIT();
        uint32_t stb = sbase + (t % 3) * ASTG;
        int j0 = t * 64;

        // ---- S = Q K^T (3-pass) ----
        float ps[8][4];
        #pragma unroll
        for (int nt = 0; nt < 8; nt++)
            #pragma unroll
            for (int e = 0; e < 4; e++) ps[nt][e] = 0.f;
        #pragma unroll
        for (int ks = 0; ks < 4; ks++) {
            int seg = ks * 2 + lseg;
            #pragma unroll
            for (int nt2 = 0; nt2 < 4; nt2++) {
                uint32_t addr = stb + AK_HI + sw_off(nt2 * 16 + lrow, seg);
                uint32_t tt[4], u[4];
                ldmatrix_x4(tt, addr);
                ldmatrix_x4(u, addr + (AK_LO - AK_HI));
                uint32_t bh0[2] = {tt[0], tt[2]}, bh1[2] = {tt[1], tt[3]};
                uint32_t bl0[2] = {u[0], u[2]}, bl1[2] = {u[1], u[3]};
                mma_bf16(ps[nt2 * 2 + 0], qfh[ks], bh0);
                mma_bf16(ps[nt2 * 2 + 0], qfh[ks], bl0);
                mma_bf16(ps[nt2 * 2 + 0], qfl[ks], bh0);
                mma_bf16(ps[nt2 * 2 + 1], qfh[ks], bh1);
                mma_bf16(ps[nt2 * 2 + 1], qfh[ks], bl1);
                mma_bf16(ps[nt2 * 2 + 1], qfl[ks], bh1);
            }
        }

        // ---- softmax weights ----
        float l0 = 0.f, l1 = 0.f;
        #pragma unroll
        for (int nt = 0; nt < 8; nt++) {
            float mk0 = Mk[j0 + nt * 8 + tg * 2], mk1 = Mk[j0 + nt * 8 + tg * 2 + 1];
            float p0 = __expf(fminf(ps[nt][0] * scale - mk0, 60.f));
            float p1 = __expf(fminf(ps[nt][1] * scale - mk1, 60.f));
            float p2 = __expf(fminf(ps[nt][2] * scale - mk0, 60.f));
            float p3 = __expf(fminf(ps[nt][3] * scale - mk1, 60.f));
            l0 += p0 + p1; l1 += p2 + p3;
            ps[nt][0] = p0; ps[nt][1] = p1; ps[nt][2] = p2; ps[nt][3] = p3;
        }
        l_run[0] += l0; l_run[1] += l1;

        // ---- O += P V (P split in regs, 3-pass) ----
        #pragma unroll
        for (int ks = 0; ks < 4; ks++) {
            uint32_t pah[4], pal[4];
            split_pack(ps[2 * ks + 0][0], ps[2 * ks + 0][1], pah[0], pal[0]);
            split_pack(ps[2 * ks + 0][2], ps[2 * ks + 0][3], pah[1], pal[1]);
            split_pack(ps[2 * ks + 1][0], ps[2 * ks + 1][1], pah[2], pal[2]);
            split_pack(ps[2 * ks + 1][2], ps[2 * ks + 1][3], pah[3], pal[3]);
            int seg = ks * 2 + lseg;
            #pragma unroll
            for (int nd2 = 0; nd2 < 4; nd2++) {
                uint32_t addr = stb + AV_HI + sw_off(nd2 * 16 + lrow, seg);
                uint32_t tt[4], u[4];
                ldmatrix_x4(tt, addr);
                ldmatrix_x4(u, addr + (AV_LO - AV_HI));
                uint32_t bh0[2] = {tt[0], tt[2]}, bh1[2] = {tt[1], tt[3]};
                uint32_t bl0[2] = {u[0], u[2]}, bl1[2] = {u[1], u[3]};
                mma_bf16(acc_o[nd2 * 2 + 0], pah, bh0);
                mma_bf16(acc_o[nd2 * 2 + 0], pah, bl0);
                mma_bf16(acc_o[nd2 * 2 + 0], pal, bh0);
                mma_bf16(acc_o[nd2 * 2 + 1], pah, bh1);
                mma_bf16(acc_o[nd2 * 2 + 1], pah, bl1);
                mma_bf16(acc_o[nd2 * 2 + 1], pal, bh1);
            }
        }
    }

    // ---- normalize and write bf16-split concat output ----
    #pragma unroll
    for (int off = 1; off <= 2; off <<= 1) {
        l_run[0] += __shfl_xor_sync(0xffffffffu, l_run[0], off);
        l_run[1] += __shfl_xor_sync(0xffffffffu, l_run[1], off);
    }
    float inv0 = 1.0f / l_run[0], inv1 = 1.0f / l_run[1];

    int srow = s0 + w * 16 + gq;
    size_t m0r = ((size_t)srow * kB + b) * kD + (size_t)h * kDH;
    size_t m1r = ((size_t)(srow + 8) * kB + b) * kD + (size_t)h * kDH;
    #pragma unroll
    for (int nt = 0; nt < 8; nt++) {
        int col = nt * 8 + tg * 2;
        uint32_t hp, lp;
        split_pack(acc_o[nt][0] * inv0, acc_o[nt][1] * inv0, hp, lp);
        *(uint32_t*)(g_oa_hi + m0r + col) = hp;
        *(uint32_t*)(g_oa_lo + m0r + col) = lp;
        split_pack(acc_o[nt][2] * inv1, acc_o[nt][3] * inv1, hp, lp);
        *(uint32_t*)(g_oa_hi + m1r + col) = hp;
        *(uint32_t*)(g_oa_lo + m1r + col) = lp;
    }
}

// ---------------------------------------------------------------------------
extern "C" void kernel_launch(void* const* d_in, const int* in_sizes, int n_in,
                              void* d_out, int out_size) {
    (void)in_sizes; (void)n_in; (void)out_size;
    const float* query = (const float*)d_in[0];
    const float* key   = (const float*)d_in[1];
    const float* value = (const float*)d_in[2];
    const int*   kmask = (const int*)  d_in[3];
    const float* Wq    = (const float*)d_in[4];
    const float* bq    = (const float*)d_in[5];
    const float* Wk    = (const float*)d_in[6];
    const float* bk    = (const float*)d_in[7];
    const float* Wv    = (const float*)d_in[8];
    const float* bvp   = (const float*)d_in[9];
    const float* Wo    = (const float*)d_in[10];
    const float* bo    = (const float*)d_in[11];
    float* out = (float*)d_out;

    cudaFuncSetAttribute(proj_mma_kernel, cudaFuncAttributeMaxDynamicSharedMemorySize, GEMM_SMEM);
    cudaFuncSetAttribute(outproj_mma_kernel, cudaFuncAttributeMaxDynamicSharedMemorySize, GEMM_SMEM);
    cudaFuncSetAttribute(attn_mma_kernel, cudaFuncAttributeMaxDynamicSharedMemorySize, ATTN_SMEM);

    const int n4_act = kS * kB * kD / 4;

    split3_kernel<<<dim3(n4_act / 256, 3), 256>>>(query, key, value, n4_act);
    transpose_wqkv_kernel<<<dim3(kDH / 32, kD / 32, 3 * kH), dim3(32, 8)>>>(Wq, Wk, Wv);
    transpose_wo_kernel<<<dim3(kD / 32, kD / 32), dim3(32, 8)>>>(Wo);

    proj_mma_kernel<<<dim3(kS / 128, 3 * kH, kB), 256, GEMM_SMEM>>>(bq, bk, bvp);

    attn_mma_kernel<<<dim3(kS / 128, kH, kB), 256, ATTN_SMEM>>>(kmask);

    outproj_mma_kernel<<<dim3((kS * kB) / 128, kD / 64), 256, GEMM_SMEM>>>(bo, out);
}

// round 12
// speedup vs baseline: 1.0487x; 1.0487x over previous
#include <cuda_runtime.h>
#include <cuda_bf16.h>
#include <math.h>
#include <cstdint>

#define kS  1024
#define kB  4
#define kD  1024
#define kH  16
#define kDH 64

// bf16 split scratch (hi + residual-lo)
__device__ __nv_bfloat16 g_qa_hi[kS*kB*kD], g_qa_lo[kS*kB*kD];   // activations
__device__ __nv_bfloat16 g_ka_hi[kS*kB*kD], g_ka_lo[kS*kB*kD];
__device__ __nv_bfloat16 g_va_hi[kS*kB*kD], g_va_lo[kS*kB*kD];
__device__ __nv_bfloat16 g_oa_hi[kS*kB*kD], g_oa_lo[kS*kB*kD];   // attn out (concat)
__device__ __nv_bfloat16 g_wq_hi[kH*kDH*kD], g_wq_lo[kH*kDH*kD]; // [h][n][k]
__device__ __nv_bfloat16 g_wk_hi[kH*kDH*kD], g_wk_lo[kH*kDH*kD];
__device__ __nv_bfloat16 g_wv_hi[kH*kDH*kD], g_wv_lo[kH*kDH*kD];
__device__ __nv_bfloat16 g_wo_hi[kD*kD],     g_wo_lo[kD*kD];     // [n][k]
// projected q/k/v in bf16 split
__device__ __nv_bfloat16 g_qp_hi[kB*kH*kS*kDH], g_qp_lo[kB*kH*kS*kDH]; // [b][h][s][dh]
__device__ __nv_bfloat16 g_kp_hi[kB*kH*kS*kDH], g_kp_lo[kB*kH*kS*kDH]; // [b][h][s][dh]
__device__ __nv_bfloat16 g_vp_hi[kB*kH*kS*kDH], g_vp_lo[kB*kH*kS*kDH]; // [b][h][dh][s]

// ===================== helpers =====================
__device__ __forceinline__ uint32_t smem_u32(const void* p) {
    uint32_t a;
    asm("{ .reg .u64 t; cvta.to.shared.u64 t, %1; cvt.u32.u64 %0, t; }" : "=r"(a) : "l"(p));
    return a;
}
__device__ __forceinline__ void ldmatrix_x4(uint32_t* r, uint32_t a) {
    asm volatile("ldmatrix.sync.aligned.m8n8.x4.shared.b16 {%0,%1,%2,%3}, [%4];"
        : "=r"(r[0]), "=r"(r[1]), "=r"(r[2]), "=r"(r[3]) : "r"(a));
}
__device__ __forceinline__ void mma_bf16(float* c, const uint32_t* a, const uint32_t* b) {
    asm volatile("mma.sync.aligned.m16n8k16.row.col.f32.bf16.bf16.f32 "
        "{%0,%1,%2,%3},{%4,%5,%6,%7},{%8,%9},{%0,%1,%2,%3};"
        : "+f"(c[0]), "+f"(c[1]), "+f"(c[2]), "+f"(c[3])
        : "r"(a[0]), "r"(a[1]), "r"(a[2]), "r"(a[3]), "r"(b[0]), "r"(b[1]));
}
__device__ __forceinline__ void split_pack(float x, float y, uint32_t& hp, uint32_t& lp) {
    __nv_bfloat16 hx = __float2bfloat16_rn(x);
    __nv_bfloat16 hy = __float2bfloat16_rn(y);
    __nv_bfloat16 lx = __float2bfloat16_rn(x - __bfloat162float(hx));
    __nv_bfloat16 ly = __float2bfloat16_rn(y - __bfloat162float(hy));
    hp = (uint32_t)__bfloat16_as_ushort(hx) | ((uint32_t)__bfloat16_as_ushort(hy) << 16);
    lp = (uint32_t)__bfloat16_as_ushort(lx) | ((uint32_t)__bfloat16_as_ushort(ly) << 16);
}
__device__ __forceinline__ void cp_async16(uint32_t saddr, const void* gptr) {
    asm volatile("cp.async.cg.shared.global [%0], [%1], 16;" :: "r"(saddr), "l"(gptr));
}
#define CP_COMMIT() asm volatile("cp.async.commit_group;" ::: "memory")
#define CP_WAIT_0() asm volatile("cp.async.wait_group 0;" ::: "memory")

// swizzled offset within a 128B-row tile: row-major, seg XOR (row&7)
__device__ __forceinline__ uint32_t sw_off(int row, int seg) {
    return (uint32_t)(row * 128 + ((seg ^ (row & 7)) << 4));
}

// ===========================================================================
// Prep 1: split q/k/v activations. grid (n4/256, 3)
// ===========================================================================
__global__ void __launch_bounds__(256) split3_kernel(
    const float* __restrict__ q, const float* __restrict__ k,
    const float* __restrict__ v, int n4)
{
    int which = blockIdx.y;
    const float* src = (which == 0) ? q : (which == 1) ? k : v;
    __nv_bfloat16* hi = (which == 0) ? g_qa_hi : (which == 1) ? g_ka_hi : g_va_hi;
    __nv_bfloat16* lo = (which == 0) ? g_qa_lo : (which == 1) ? g_ka_lo : g_va_lo;
    int i = blockIdx.x * blockDim.x + threadIdx.x;
    if (i >= n4) return;
    float4 vv = ((const float4*)src)[i];
    uint32_t h0, l0, h1, l1;
    split_pack(vv.x, vv.y, h0, l0);
    split_pack(vv.z, vv.w, h1, l1);
    *(uint2*)(hi + (size_t)i * 4) = make_uint2(h0, h1);
    *(uint2*)(lo + (size_t)i * 4) = make_uint2(l0, l1);
}

// ===========================================================================
// Prep 2: transpose+split weights
// ===========================================================================
__global__ void __launch_bounds__(256) transpose_wqkv_kernel(
    const float* __restrict__ Wq, const float* __restrict__ Wk,
    const float* __restrict__ Wv)
{
    __shared__ float tile[32][33];
    int which = blockIdx.z >> 4;
    int h = blockIdx.z & 15;
    const float* src = ((which == 0) ? Wq : (which == 1) ? Wk : Wv) + (size_t)h * kD * kDH;
    __nv_bfloat16* hi = ((which == 0) ? g_wq_hi : (which == 1) ? g_wk_hi : g_wv_hi) + (size_t)h * kDH * kD;
    __nv_bfloat16* lo = ((which == 0) ? g_wq_lo : (which == 1) ? g_wk_lo : g_wv_lo) + (size_t)h * kDH * kD;
    int c0 = blockIdx.x * 32, r0 = blockIdx.y * 32;
    int tx = threadIdx.x, ty = threadIdx.y;
    #pragma unroll
    for (int i = 0; i < 4; i++)
        tile[ty + i * 8][tx] = src[(size_t)(r0 + ty + i * 8) * kDH + c0 + tx];
    __syncthreads();
    #pragma unroll
    for (int i = 0; i < 4; i++) {
        float v = tile[tx][ty + i * 8];
        __nv_bfloat16 hv = __float2bfloat16_rn(v);
        __nv_bfloat16 lv = __float2bfloat16_rn(v - __bfloat162float(hv));
        size_t o = (size_t)(c0 + ty + i * 8) * kD + r0 + tx;
        hi[o] = hv;
        lo[o] = lv;
    }
}

__global__ void __launch_bounds__(256) transpose_wo_kernel(const float* __restrict__ Wo)
{
    __shared__ float tile[32][33];
    int c0 = blockIdx.x * 32, r0 = blockIdx.y * 32;
    int tx = threadIdx.x, ty = threadIdx.y;
    #pragma unroll
    for (int i = 0; i < 4; i++)
        tile[ty + i * 8][tx] = Wo[(size_t)(r0 + ty + i * 8) * kD + c0 + tx];
    __syncthreads();
    #pragma unroll
    for (int i = 0; i < 4; i++) {
        float v = tile[tx][ty + i * 8];
        __nv_bfloat16 hv = __float2bfloat16_rn(v);
        __nv_bfloat16 lv = __float2bfloat16_rn(v - __bfloat162float(hv));
        size_t o = (size_t)(c0 + ty + i * 8) * kD + r0 + tx;
        g_wo_hi[o] = hv;
        g_wo_lo[o] = lv;
    }
}

// ===========================================================================
// mma.sync GEMM, 2-stage cp.async pipeline, XOR-swizzled smem, 1 sync/chunk.
// BM=128, BN=64, BK=64, 256 thr. Stage: A_hi 0, A_lo 16384, B_hi 32768,
// B_lo 40960; stage size 49152. Two stages = 96KB -> 2 CTAs/SM.
// Loop order per chunk: wait(c) -> sync -> issue load(c+1) -> compute(c).
// load(c+1) writes stage (c+1)&1 whose readers (compute(c-1)) are past the
// sync; compute(c) reads stage c&1. Single barrier per chunk.
// ===========================================================================
#define SA0 0
#define SA1 16384
#define SB0 32768
#define SB1 40960
#define STG_SZ 49152
#define GEMM_SMEM (2 * STG_SZ)   // 98304

__device__ __forceinline__ void gemm_compute_chunk(
    uint32_t stb, int wm, int wn, int lane, float acc[2][4][4])
{
    int lrow = lane & 15;
    int lseg = lane >> 4;
    #pragma unroll
    for (int ks = 0; ks < 4; ks++) {
        int seg = ks * 2 + lseg;
        uint32_t a0f[2][4], a1f[2][4], b0f[4][2], b1f[4][2];
        #pragma unroll
        for (int mt = 0; mt < 2; mt++) {
            uint32_t addr = stb + SA0 + sw_off(wm * 32 + mt * 16 + lrow, seg);
            ldmatrix_x4(a0f[mt], addr);
            ldmatrix_x4(a1f[mt], addr + (SA1 - SA0));
        }
        #pragma unroll
        for (int nt2 = 0; nt2 < 2; nt2++) {
            uint32_t addr = stb + SB0 + sw_off(wn * 32 + nt2 * 16 + lrow, seg);
            uint32_t t[4];
            ldmatrix_x4(t, addr);
            b0f[nt2 * 2 + 0][0] = t[0]; b0f[nt2 * 2 + 0][1] = t[2];
            b0f[nt2 * 2 + 1][0] = t[1]; b0f[nt2 * 2 + 1][1] = t[3];
            ldmatrix_x4(t, addr + (SB1 - SB0));
            b1f[nt2 * 2 + 0][0] = t[0]; b1f[nt2 * 2 + 0][1] = t[2];
            b1f[nt2 * 2 + 1][0] = t[1]; b1f[nt2 * 2 + 1][1] = t[3];
        }
        #pragma unroll
        for (int mt = 0; mt < 2; mt++)
            #pragma unroll
            for (int nt = 0; nt < 4; nt++) {
                mma_bf16(acc[mt][nt], a0f[mt], b0f[nt]);
                mma_bf16(acc[mt][nt], a0f[mt], b1f[nt]);
                mma_bf16(acc[mt][nt], a1f[mt], b0f[nt]);
            }
    }
}

// ---- fused projections. grid (8, 48, 4): y -> which*16+h ----
__global__ void __launch_bounds__(256) proj_mma_kernel(
    const float* __restrict__ bq, const float* __restrict__ bk,
    const float* __restrict__ bv)
{
    extern __shared__ char smem[];
    uint32_t sbase = smem_u32(smem);
    int s0 = blockIdx.x * 128;
    int which = blockIdx.y >> 4;
    int h  = blockIdx.y & 15;
    int b  = blockIdx.z;
    int tid = threadIdx.x;
    int wid = tid >> 5, lane = tid & 31;
    int wm = wid >> 1, wn = wid & 1;

    const __nv_bfloat16* a_hi = (which == 0) ? g_qa_hi : (which == 1) ? g_ka_hi : g_va_hi;
    const __nv_bfloat16* a_lo = (which == 0) ? g_qa_lo : (which == 1) ? g_ka_lo : g_va_lo;
    const __nv_bfloat16* w_hi = (which == 0) ? g_wq_hi : (which == 1) ? g_wk_hi : g_wv_hi;
    const __nv_bfloat16* w_lo = (which == 0) ? g_wq_lo : (which == 1) ? g_wk_lo : g_wv_lo;
    const float* bias = (which == 0) ? bq : (which == 1) ? bk : bv;

    float acc[2][4][4];
    #pragma unroll
    for (int mt = 0; mt < 2; mt++)
        #pragma unroll
        for (int nt = 0; nt < 4; nt++)
            #pragma unroll
            for (int e = 0; e < 4; e++) acc[mt][nt][e] = 0.f;

    auto load_chunk = [&](int c, int stg) {
        uint32_t stb = sbase + stg * STG_SZ;
        int k0 = c * 64;
        #pragma unroll
        for (int i = 0; i < 4; i++) {
            int id = tid + i * 256;
            int m = id >> 3, k8 = id & 7;
            size_t g = ((size_t)(s0 + m) * kB + b) * kD + k0 + k8 * 8;
            uint32_t d = stb + sw_off(m, k8);
            cp_async16(d + SA0, a_hi + g);
            cp_async16(d + SA1, a_lo + g);
        }
        #pragma unroll
        for (int i = 0; i < 2; i++) {
            int id = tid + i * 256;
            int n = id >> 3, k8 = id & 7;
            size_t g = ((size_t)h * kDH + n) * kD + k0 + k8 * 8;
            uint32_t d = stb + sw_off(n, k8);
            cp_async16(d + SB0, w_hi + g);
            cp_async16(d + SB1, w_lo + g);
        }
    };

    load_chunk(0, 0);
    CP_COMMIT();
    for (int c = 0; c < 16; c++) {
        CP_WAIT_0();
        __syncthreads();
        if (c + 1 < 16) {
            load_chunk(c + 1, (c + 1) & 1);
            CP_COMMIT();
        }
        gemm_compute_chunk(sbase + (c & 1) * STG_SZ, wm, wn, lane, acc);
    }

    int gq = lane >> 2, tg = lane & 3;
    size_t bh = (size_t)b * kH + h;
    if (which < 2) {
        __nv_bfloat16* oh = (which == 0) ? g_qp_hi : g_kp_hi;
        __nv_bfloat16* ol = (which == 0) ? g_qp_lo : g_kp_lo;
        #pragma unroll
        for (int mt = 0; mt < 2; mt++) {
            int row0 = s0 + wm * 32 + mt * 16 + gq;
            #pragma unroll
            for (int nt = 0; nt < 4; nt++) {
                int col = wn * 32 + nt * 8 + tg * 2;
                float b0 = bias[h * kDH + col], b1 = bias[h * kDH + col + 1];
                uint32_t hp, lp;
                size_t off0 = (bh * kS + row0) * kDH + col;
                split_pack(acc[mt][nt][0] + b0, acc[mt][nt][1] + b1, hp, lp);
                *(uint32_t*)(oh + off0) = hp; *(uint32_t*)(ol + off0) = lp;
                split_pack(acc[mt][nt][2] + b0, acc[mt][nt][3] + b1, hp, lp);
                size_t off1 = off0 + (size_t)8 * kDH;
                *(uint32_t*)(oh + off1) = hp; *(uint32_t*)(ol + off1) = lp;
            }
        }
    } else {
        #pragma unroll
        for (int mt = 0; mt < 2; mt++) {
            int row0 = s0 + wm * 32 + mt * 16 + gq;
            #pragma unroll
            for (int nt = 0; nt < 4; nt++) {
                int col = wn * 32 + nt * 8 + tg * 2;
                float b0 = bias[h * kDH + col], b1 = bias[h * kDH + col + 1];
                float vals[4] = {acc[mt][nt][0] + b0, acc[mt][nt][1] + b1,
                                 acc[mt][nt][2] + b0, acc[mt][nt][3] + b1};
                int rr[4] = {row0, row0, row0 + 8, row0 + 8};
                int cc[4] = {col, col + 1, col, col + 1};
                #pragma unroll
                for (int e = 0; e < 4; e++) {
                    __nv_bfloat16 hv = __float2bfloat16_rn(vals[e]);
                    __nv_bfloat16 lv = __float2bfloat16_rn(vals[e] - __bfloat162float(hv));
                    size_t off = (bh * kDH + cc[e]) * kS + rr[e];
                    g_vp_hi[off] = hv;
                    g_vp_lo[off] = lv;
                }
            }
        }
    }
}

// ---- output projection ----
__global__ void __launch_bounds__(256) outproj_mma_kernel(
    const float* __restrict__ bo, float* __restrict__ out)
{
    extern __shared__ char smem[];
    uint32_t sbase = smem_u32(smem);
    int m0 = blockIdx.x * 128;
    int n0 = blockIdx.y * 64;
    int tid = threadIdx.x;
    int wid = tid >> 5, lane = tid & 31;
    int wm = wid >> 1, wn = wid & 1;

    float acc[2][4][4];
    #pragma unroll
    for (int mt = 0; mt < 2; mt++)
        #pragma unroll
        for (int nt = 0; nt < 4; nt++)
            #pragma unroll
            for (int e = 0; e < 4; e++) acc[mt][nt][e] = 0.f;

    auto load_chunk = [&](int c, int stg) {
        uint32_t stb = sbase + stg * STG_SZ;
        int k0 = c * 64;
        #pragma unroll
        for (int i = 0; i < 4; i++) {
            int id = tid + i * 256;
            int m = id >> 3, k8 = id & 7;
            size_t g = (size_t)(m0 + m) * kD + k0 + k8 * 8;
            uint32_t d = stb + sw_off(m, k8);
            cp_async16(d + SA0, g_oa_hi + g);
            cp_async16(d + SA1, g_oa_lo + g);
        }
        #pragma unroll
        for (int i = 0; i < 2; i++) {
            int id = tid + i * 256;
            int n = id >> 3, k8 = id & 7;
            size_t g = (size_t)(n0 + n) * kD + k0 + k8 * 8;
            uint32_t d = stb + sw_off(n, k8);
            cp_async16(d + SB0, g_wo_hi + g);
            cp_async16(d + SB1, g_wo_lo + g);
        }
    };

    load_chunk(0, 0);
    CP_COMMIT();
    for (int c = 0; c < 16; c++) {
        CP_WAIT_0();
        __syncthreads();
        if (c + 1 < 16) {
            load_chunk(c + 1, (c + 1) & 1);
            CP_COMMIT();
        }
        gemm_compute_chunk(sbase + (c & 1) * STG_SZ, wm, wn, lane, acc);
    }

    int gq = lane >> 2, tg = lane & 3;
    #pragma unroll
    for (int mt = 0; mt < 2; mt++) {
        int row = m0 + wm * 32 + mt * 16 + gq;
        #pragma unroll
        for (int nt = 0; nt < 4; nt++) {
            int col = n0 + wn * 32 + nt * 8 + tg * 2;
            float b0 = bo[col], b1 = bo[col + 1];
            size_t r0 = (size_t)row * kD + col;
            *(float2*)(out + r0) = make_float2(acc[mt][nt][0] + b0, acc[mt][nt][1] + b1);
            *(float2*)(out + r0 + 8 * kD) = make_float2(acc[mt][nt][2] + b0, acc[mt][nt][3] + b1);
        }
    }
}

// ===========================================================================
// Tensor-core attention, swizzled smem, 2-stage cp.async K/V pipeline,
// 1 sync/tile (same reordered loop). Stage: K_hi 0, K_lo 8192, V_hi 16384,
// V_lo 24576; stage 32768. Mask at 65536 (4KB). Total 69.6KB -> 3 CTAs/SM.
// ===========================================================================
#define AK_HI 0
#define AK_LO 8192
#define AV_HI 16384
#define AV_LO 24576
#define ASTG  32768
#define AMK   65536
#define ATTN_SMEM (65536 + 4096)

__global__ void __launch_bounds__(256) attn_mma_kernel(const int* __restrict__ mask)
{
    extern __shared__ char smem[];
    uint32_t sbase = smem_u32(smem);
    int s0 = blockIdx.x * 128;
    int h  = blockIdx.y;
    int b  = blockIdx.z;
    int tid = threadIdx.x;
    int w = tid >> 5, lane = tid & 31;
    int gq = lane >> 2, tg = lane & 3;
    size_t bh = (size_t)b * kH + h;

    const __nv_bfloat16* qh = g_qp_hi + bh * kS * kDH;
    const __nv_bfloat16* ql = g_qp_lo + bh * kS * kDH;
    const __nv_bfloat16* kh = g_kp_hi + bh * kS * kDH;
    const __nv_bfloat16* kl = g_kp_lo + bh * kS * kDH;
    const __nv_bfloat16* vth = g_vp_hi + bh * kDH * kS;  // [dh][s]
    const __nv_bfloat16* vtl = g_vp_lo + bh * kDH * kS;

    // ---- mask preload ----
    float* Mk = (float*)(smem + AMK);
    for (int idx = tid; idx < kS; idx += 256)
        Mk[idx] = (float)mask[(size_t)idx * kB + b] * 1e18f;

    // ---- stage Q tile (128 rows hi at 0, lo at 16384; swizzled) ----
    #pragma unroll
    for (int i = 0; i < 4; i++) {
        int id = tid + i * 256;
        int row = id >> 3, k8 = id & 7;
        size_t g = (size_t)(s0 + row) * kDH + k8 * 8;
        uint32_t d = sbase + sw_off(row, k8);
        cp_async16(d, qh + g);
        cp_async16(d + 16384, ql + g);
    }
    CP_COMMIT();
    CP_WAIT_0();
    __syncthreads();
    uint32_t qfh[4][4], qfl[4][4];
    int lrow = lane & 15, lseg = lane >> 4;
    #pragma unroll
    for (int ks = 0; ks < 4; ks++) {
        uint32_t addr = sbase + sw_off(w * 16 + lrow, ks * 2 + lseg);
        ldmatrix_x4(qfh[ks], addr);
        ldmatrix_x4(qfl[ks], addr + 16384);
    }
    __syncthreads();  // Q reads done before stage reuse

    float acc_o[8][4];
    #pragma unroll
    for (int nt = 0; nt < 8; nt++)
        #pragma unroll
        for (int e = 0; e < 4; e++) acc_o[nt][e] = 0.f;
    float l_run[2] = {0.f, 0.f};
    const float scale = 0.125f;

    auto load_tile = [&](int t, int stg) {
        uint32_t stb = sbase + stg * ASTG;
        int j0 = t * 64;
        #pragma unroll
        for (int i = 0; i < 8; i++) {
            int id = tid + (i & 1) * 256;
            int row = id >> 3, k8 = id & 7;
            const __nv_bfloat16* src;
            uint32_t dst;
            if (i < 2)      { src = kh  + (size_t)(j0 + row) * kDH + k8 * 8; dst = AK_HI; }
            else if (i < 4) { src = kl  + (size_t)(j0 + row) * kDH + k8 * 8; dst = AK_LO; }
            else if (i < 6) { src = vth + (size_t)row * kS + j0 + k8 * 8;    dst = AV_HI; }
            else            { src = vtl + (size_t)row * kS + j0 + k8 * 8;    dst = AV_LO; }
            cp_async16(stb + dst + sw_off(row, k8), src);
        }
    };

    load_tile(0, 0);
    CP_COMMIT();
    for (int t = 0; t < 16; t++) {
        CP_WAIT_0();
        __syncthreads();
        if (t + 1 < 16) {
            load_tile(t + 1, (t + 1) & 1);
            CP_COMMIT();
        }
        uint32_t stb = sbase + (t & 1) * ASTG;
        int j0 = t * 64;

        // ---- S = Q K^T (3-pass) ----
        float ps[8][4];
        #pragma unroll
        for (int nt = 0; nt < 8; nt++)
            #pragma unroll
            for (int e = 0; e < 4; e++) ps[nt][e] = 0.f;
        #pragma unroll
        for (int ks = 0; ks < 4; ks++) {
            int seg = ks * 2 + lseg;
            #pragma unroll
            for (int nt2 = 0; nt2 < 4; nt2++) {
                uint32_t addr = stb + AK_HI + sw_off(nt2 * 16 + lrow, seg);
                uint32_t tt[4], u[4];
                ldmatrix_x4(tt, addr);
                ldmatrix_x4(u, addr + (AK_LO - AK_HI));
                uint32_t bh0[2] = {tt[0], tt[2]}, bh1[2] = {tt[1], tt[3]};
                uint32_t bl0[2] = {u[0], u[2]}, bl1[2] = {u[1], u[3]};
                mma_bf16(ps[nt2 * 2 + 0], qfh[ks], bh0);
                mma_bf16(ps[nt2 * 2 + 0], qfh[ks], bl0);
                mma_bf16(ps[nt2 * 2 + 0], qfl[ks], bh0);
                mma_bf16(ps[nt2 * 2 + 1], qfh[ks], bh1);
                mma_bf16(ps[nt2 * 2 + 1], qfh[ks], bl1);
                mma_bf16(ps[nt2 * 2 + 1], qfl[ks], bh1);
            }
        }

        // ---- softmax weights ----
        float l0 = 0.f, l1 = 0.f;
        #pragma unroll
        for (int nt = 0; nt < 8; nt++) {
            float mk0 = Mk[j0 + nt * 8 + tg * 2], mk1 = Mk[j0 + nt * 8 + tg * 2 + 1];
            float p0 = __expf(fminf(ps[nt][0] * scale - mk0, 60.f));
            float p1 = __expf(fminf(ps[nt][1] * scale - mk1, 60.f));
            float p2 = __expf(fminf(ps[nt][2] * scale - mk0, 60.f));
            float p3 = __expf(fminf(ps[nt][3] * scale - mk1, 60.f));
            l0 += p0 + p1; l1 += p2 + p3;
            ps[nt][0] = p0; ps[nt][1] = p1; ps[nt][2] = p2; ps[nt][3] = p3;
        }
        l_run[0] += l0; l_run[1] += l1;

        // ---- O += P V (P split in regs, 3-pass) ----
        #pragma unroll
        for (int ks = 0; ks < 4; ks++) {
            uint32_t pah[4], pal[4];
            split_pack(ps[2 * ks + 0][0], ps[2 * ks + 0][1], pah[0], pal[0]);
            split_pack(ps[2 * ks + 0][2], ps[2 * ks + 0][3], pah[1], pal[1]);
            split_pack(ps[2 * ks + 1][0], ps[2 * ks + 1][1], pah[2], pal[2]);
            split_pack(ps[2 * ks + 1][2], ps[2 * ks + 1][3], pah[3], pal[3]);
            int seg = ks * 2 + lseg;
            #pragma unroll
            for (int nd2 = 0; nd2 < 4; nd2++) {
                uint32_t addr = stb + AV_HI + sw_off(nd2 * 16 + lrow, seg);
                uint32_t tt[4], u[4];
                ldmatrix_x4(tt, addr);
                ldmatrix_x4(u, addr + (AV_LO - AV_HI));
                uint32_t bh0[2] = {tt[0], tt[2]}, bh1[2] = {tt[1], tt[3]};
                uint32_t bl0[2] = {u[0], u[2]}, bl1[2] = {u[1], u[3]};
                mma_bf16(acc_o[nd2 * 2 + 0], pah, bh0);
                mma_bf16(acc_o[nd2 * 2 + 0], pah, bl0);
                mma_bf16(acc_o[nd2 * 2 + 0], pal, bh0);
                mma_bf16(acc_o[nd2 * 2 + 1], pah, bh1);
                mma_bf16(acc_o[nd2 * 2 + 1], pah, bl1);
                mma_bf16(acc_o[nd2 * 2 + 1], pal, bh1);
            }
        }
    }

    // ---- normalize and write bf16-split concat output ----
    #pragma unroll
    for (int off = 1; off <= 2; off <<= 1) {
        l_run[0] += __shfl_xor_sync(0xffffffffu, l_run[0], off);
        l_run[1] += __shfl_xor_sync(0xffffffffu, l_run[1], off);
    }
    float inv0 = 1.0f / l_run[0], inv1 = 1.0f / l_run[1];

    int srow = s0 + w * 16 + gq;
    size_t m0r = ((size_t)srow * kB + b) * kD + (size_t)h * kDH;
    size_t m1r = ((size_t)(srow + 8) * kB + b) * kD + (size_t)h * kDH;
    #pragma unroll
    for (int nt = 0; nt < 8; nt++) {
        int col = nt * 8 + tg * 2;
        uint32_t hp, lp;
        split_pack(acc_o[nt][0] * inv0, acc_o[nt][1] * inv0, hp, lp);
        *(uint32_t*)(g_oa_hi + m0r + col) = hp;
        *(uint32_t*)(g_oa_lo + m0r + col) = lp;
        split_pack(acc_o[nt][2] * inv1, acc_o[nt][3] * inv1, hp, lp);
        *(uint32_t*)(g_oa_hi + m1r + col) = hp;
        *(uint32_t*)(g_oa_lo + m1r + col) = lp;
    }
}

// ---------------------------------------------------------------------------
extern "C" void kernel_launch(void* const* d_in, const int* in_sizes, int n_in,
                              void* d_out, int out_size) {
    (void)in_sizes; (void)n_in; (void)out_size;
    const float* query = (const float*)d_in[0];
    const float* key   = (const float*)d_in[1];
    const float* value = (const float*)d_in[2];
    const int*   kmask = (const int*)  d_in[3];
    const float* Wq    = (const float*)d_in[4];
    const float* bq    = (const float*)d_in[5];
    const float* Wk    = (const float*)d_in[6];
    const float* bk    = (const float*)d_in[7];
    const float* Wv    = (const float*)d_in[8];
    const float* bvp   = (const float*)d_in[9];
    const float* Wo    = (const float*)d_in[10];
    const float* bo    = (const float*)d_in[11];
    float* out = (float*)d_out;

    cudaFuncSetAttribute(proj_mma_kernel, cudaFuncAttributeMaxDynamicSharedMemorySize, GEMM_SMEM);
    cudaFuncSetAttribute(outproj_mma_kernel, cudaFuncAttributeMaxDynamicSharedMemorySize, GEMM_SMEM);
    cudaFuncSetAttribute(attn_mma_kernel, cudaFuncAttributeMaxDynamicSharedMemorySize, ATTN_SMEM);

    const int n4_act = kS * kB * kD / 4;

    split3_kernel<<<dim3(n4_act / 256, 3), 256>>>(query, key, value, n4_act);
    transpose_wqkv_kernel<<<dim3(kDH / 32, kD / 32, 3 * kH), dim3(32, 8)>>>(Wq, Wk, Wv);
    transpose_wo_kernel<<<dim3(kD / 32, kD / 32), dim3(32, 8)>>>(Wo);

    proj_mma_kernel<<<dim3(kS / 128, 3 * kH, kB), 256, GEMM_SMEM>>>(bq, bk, bvp);

    attn_mma_kernel<<<dim3(kS / 128, kH, kB), 256, ATTN_SMEM>>>(kmask);

    outproj_mma_kernel<<<dim3((kS * kB) / 128, kD / 64), 256, GEMM_SMEM>>>(bo, out);
}